// round 6
// baseline (speedup 1.0000x reference)
#include <cuda_runtime.h>
#include <cstdint>

#define BATCHN 1024
#define NIMG   2048

// ---- per-CTA smem layout (bytes) ----
#define SM_T     0          // 64 x 128 f32 = 32768
#define SM_Z     32768      // 2 x 16384 z chunk ring (32 a-rows each)
#define SM_FY    65536      // 64 x 128 f32
#define SM_MBAR  98304      // 2 mbarriers
#define SMEM_TOTAL 98320

typedef unsigned long long ull;

__device__ float g_FY[64 * 128];    // F_Y normalized, gamma folded
__device__ float g_FXT[128 * 64];   // F_X[m][b] stored as [b][m]

// ======================= setup kernel =======================
__global__ void setup_kernel(const float* __restrict__ hrow,
                             const float* __restrict__ W,
                             const float* __restrict__ bias) {
    __shared__ float red[256];
    __shared__ float sc[8];
    int tid = threadIdx.x;

    for (int j = 0; j < 5; j++) {
        float s = 0.f;
        for (int k = tid; k < 1024; k += 256) s += hrow[k] * W[j * 1024 + k];
        red[tid] = s; __syncthreads();
        for (int o = 128; o > 0; o >>= 1) { if (tid < o) red[tid] += red[tid + o]; __syncthreads(); }
        if (tid == 0) sc[j] = red[0] + bias[j];
        __syncthreads();
    }

    if (tid == 0) {
        float gtX = sc[0], gtY = sc[1], log_var = sc[2], log_dt = sc[3], lg = sc[4];
        sc[0] = 129.f * (gtX + 1.f) * 0.5f;          // g_X
        sc[1] = 129.f * (gtY + 1.f) * 0.5f;          // g_Y
        sc[2] = expf(log_var + 1e-8f);               // var
        sc[3] = expf(log_dt) * (127.f / 63.f);       // d
        sc[4] = expf(lg);                            // gamma
    }
    __syncthreads();
    float gX = sc[0], gY = sc[1], var = sc[2], dd = sc[3], gamma = sc[4];

    float partY = 0.f;
    for (int idx = tid; idx < 8192; idx += 256) {
        int n = idx >> 7, c = idx & 127;
        float mu = gY + ((float)n - 32.5f) * dd;
        float df = (float)c - mu;
        float e = expf(-(df * df) / (2.0f * var));
        g_FY[idx] = e; partY += e;
    }
    red[tid] = partY; __syncthreads();
    for (int o = 128; o > 0; o >>= 1) { if (tid < o) red[tid] += red[tid + o]; __syncthreads(); }
    if (tid == 0) sc[5] = red[0];
    __syncthreads();

    float partX = 0.f;
    for (int idx = tid; idx < 8192; idx += 256) {
        int m = idx >> 7, c = idx & 127;
        float mu = gX + ((float)m - 32.5f) * dd;
        float df = (float)c - mu;
        float e = expf(-(df * df) / (2.0f * var));
        g_FXT[c * 64 + m] = e; partX += e;
    }
    red[tid] = partX; __syncthreads();
    for (int o = 128; o > 0; o >>= 1) { if (tid < o) red[tid] += red[tid + o]; __syncthreads(); }
    if (tid == 0) sc[6] = red[0];
    __syncthreads();

    float sY = gamma / sc[5];
    float sX = 1.0f / sc[6];
    for (int idx = tid; idx < 8192; idx += 256) {
        g_FY[idx]  *= sY;
        g_FXT[idx] *= sX;
    }
}

// ======================= helpers =======================
__device__ __forceinline__ uint32_t smem_u32(const void* p) {
    uint32_t a;
    asm("{ .reg .u64 t; cvta.to.shared.u64 t, %1; cvt.u32.u64 %0, t; }" : "=r"(a) : "l"(p));
    return a;
}
__device__ __forceinline__ ull dup2(float f) {
    ull r;
    asm("mov.b64 %0, {%1, %1};" : "=l"(r) : "f"(f));
    return r;
}
__device__ __forceinline__ void unpack2(ull v, float& lo, float& hi) {
    asm("mov.b64 {%0, %1}, %2;" : "=f"(lo), "=f"(hi) : "l"(v));
}
__device__ __forceinline__ void fma2(ull& c, ull a, ull b) {
    asm("fma.rn.f32x2 %0, %1, %2, %0;" : "+l"(c) : "l"(a), "l"(b));
}
__device__ __forceinline__ void mbar_wait(uint32_t addr, uint32_t parity) {
    asm volatile(
        "{\n\t.reg .pred P;\n\t"
        "LAB_%=:\n\t"
        "mbarrier.try_wait.parity.acquire.cta.shared::cta.b64 P, [%0], %1, 0x989680;\n\t"
        "@P bra.uni DONE_%=;\n\t"
        "bra.uni LAB_%=;\n\t"
        "DONE_%=:\n\t}"
        :: "r"(addr), "r"(parity) : "memory");
}
__device__ __forceinline__ void bulk_load(uint32_t dst, const float* src, uint32_t mbar) {
    asm volatile("mbarrier.arrive.expect_tx.shared.b64 _, [%0], %1;"
                 :: "r"(mbar), "r"(16384u) : "memory");
    asm volatile("cp.async.bulk.shared::cta.global.mbarrier::complete_tx::bytes [%0], [%1], %2, [%3];"
                 :: "r"(dst), "l"(src), "r"(16384u), "r"(mbar) : "memory");
}

// chunk c (CTA-local counter): image = img0 + (c>>2)*grid, quarter = c&3
__device__ __forceinline__ const float* chunk_src(int c, int img0, int grid,
                                                  const float* x, const float* xh, int& img) {
    img = img0 + (c >> 2) * grid;
    const float* base = (img < BATCHN) ? x + (size_t)img * 16384
                                       : xh + (size_t)(img - BATCHN) * 16384;
    return base + (c & 3) * 4096;
}

// ======================= main kernel =======================
__global__ void __launch_bounds__(256, 2)
main_kernel(const float* __restrict__ x, const float* __restrict__ xh,
            float* __restrict__ out, int grid) {
    extern __shared__ __align__(16) char smem[];
    float* sT  = (float*)(smem + SM_T);
    float* sFY = (float*)(smem + SM_FY);
    int tid = threadIdx.x;

    // stage F_Y into smem
    for (int i = tid; i < 8192; i += 256) sFY[i] = g_FY[i];

    uint32_t mb  = smem_u32(smem + SM_MBAR);
    uint32_t zsm = smem_u32(smem + SM_Z);
    if (tid == 0) {
        asm volatile("mbarrier.init.shared.b64 [%0], 1;" :: "r"(mb));
        asm volatile("mbarrier.init.shared.b64 [%0], 1;" :: "r"(mb + 8));
        asm volatile("fence.proxy.async.shared::cta;" ::: "memory");
    }
    __syncthreads();

    int img0 = blockIdx.x;
    if (tid == 0) {
        int im;
        const float* s0 = chunk_src(0, img0, grid, x, xh, im);
        if (im < NIMG) bulk_load(zsm, s0, mb);
        const float* s1 = chunk_src(1, img0, grid, x, xh, im);
        if (im < NIMG) bulk_load(zsm + 16384u, s1, mb + 8);
    }

    const int bx = tid & 15, ny = tid >> 4;   // stage-1 map
    const int g  = tid & 7,  nh = tid >> 3;   // stage-2 map

    // per-thread FY row pointers (ull pairs over a)
    const ull* fy0 = (const ull*)(sFY + (ny * 4 + 0) * 128);
    const ull* fy1 = (const ull*)(sFY + (ny * 4 + 1) * 128);
    const ull* fy2p = (const ull*)(sFY + (ny * 4 + 2) * 128);
    const ull* fy3 = (const ull*)(sFY + (ny * 4 + 3) * 128);

    int it = 0;
    for (int img = img0; img < NIMG; img += grid, it++) {

        // ---- stage 1: t[n][b] = sum_a FY[n][a] * z[a][b], chunked over a ----
        ull acc[4][4];
#pragma unroll
        for (int i = 0; i < 4; i++)
#pragma unroll
            for (int j = 0; j < 4; j++) acc[i][j] = 0ull;

        for (int h = 0; h < 4; h++) {
            int c = it * 4 + h;
            mbar_wait(mb + (c & 1) * 8, (uint32_t)((c >> 1) & 1));
            const ull* zc = (const ull*)(smem + SM_Z + (c & 1) * 16384);

#pragma unroll 4
            for (int ap = 0; ap < 16; ap++) {
                const ull* zr0 = zc + (2 * ap) * 64;
                const ull* zr1 = zc + (2 * ap + 1) * 64;
                ull z00 = zr0[bx], z01 = zr0[bx + 16], z02 = zr0[bx + 32], z03 = zr0[bx + 48];
                ull z10 = zr1[bx], z11 = zr1[bx + 16], z12 = zr1[bx + 32], z13 = zr1[bx + 48];
                int aq = h * 16 + ap;
                ull fp0 = fy0[aq], fp1 = fy1[aq], fp2 = fy2p[aq], fp3 = fy3[aq];
                float lo, hi;
                unpack2(fp0, lo, hi);
                { ull d0 = dup2(lo), d1 = dup2(hi);
                  fma2(acc[0][0], d0, z00); fma2(acc[0][1], d0, z01);
                  fma2(acc[0][2], d0, z02); fma2(acc[0][3], d0, z03);
                  fma2(acc[0][0], d1, z10); fma2(acc[0][1], d1, z11);
                  fma2(acc[0][2], d1, z12); fma2(acc[0][3], d1, z13); }
                unpack2(fp1, lo, hi);
                { ull d0 = dup2(lo), d1 = dup2(hi);
                  fma2(acc[1][0], d0, z00); fma2(acc[1][1], d0, z01);
                  fma2(acc[1][2], d0, z02); fma2(acc[1][3], d0, z03);
                  fma2(acc[1][0], d1, z10); fma2(acc[1][1], d1, z11);
                  fma2(acc[1][2], d1, z12); fma2(acc[1][3], d1, z13); }
                unpack2(fp2, lo, hi);
                { ull d0 = dup2(lo), d1 = dup2(hi);
                  fma2(acc[2][0], d0, z00); fma2(acc[2][1], d0, z01);
                  fma2(acc[2][2], d0, z02); fma2(acc[2][3], d0, z03);
                  fma2(acc[2][0], d1, z10); fma2(acc[2][1], d1, z11);
                  fma2(acc[2][2], d1, z12); fma2(acc[2][3], d1, z13); }
                unpack2(fp3, lo, hi);
                { ull d0 = dup2(lo), d1 = dup2(hi);
                  fma2(acc[3][0], d0, z00); fma2(acc[3][1], d0, z01);
                  fma2(acc[3][2], d0, z02); fma2(acc[3][3], d0, z03);
                  fma2(acc[3][0], d1, z10); fma2(acc[3][1], d1, z11);
                  fma2(acc[3][2], d1, z12); fma2(acc[3][3], d1, z13); }
            }
            __syncthreads();   // chunk buffer fully consumed
            int cn = c + 2;
            if (tid == 0) {
                int im;
                const float* s = chunk_src(cn, img0, grid, x, xh, im);
                if (im < NIMG) bulk_load(zsm + (cn & 1) * 16384u, s, mb + (cn & 1) * 8);
            }
        }

        // write t to smem (unpadded 64x128)
#pragma unroll
        for (int i = 0; i < 4; i++)
#pragma unroll
            for (int j = 0; j < 4; j++) {
                int n = ny * 4 + i, bp = bx + 16 * j;
                *(ull*)(sT + n * 128 + 2 * bp) = acc[i][j];
            }
        __syncthreads();

        // ---- stage 2: out[n][m] = sum_b t[n][b] * FXT[b][m] ----
        // FXT from global (L1-resident), ulonglong2 loads
        ull a2[2][4];
#pragma unroll
        for (int i = 0; i < 2; i++)
#pragma unroll
            for (int j = 0; j < 4; j++) a2[i][j] = 0ull;

        const ulonglong2* fx = (const ulonglong2*)g_FXT;   // 16 per row of 64 floats
#pragma unroll 4
        for (int b = 0; b < 128; b++) {
            ulonglong2 A = __ldg(fx + b * 16 + g);        // m 4g..4g+3
            ulonglong2 B = __ldg(fx + b * 16 + g + 8);    // m 4g+32..4g+35
            ull t0 = dup2(sT[(nh * 2 + 0) * 128 + b]);
            ull t1 = dup2(sT[(nh * 2 + 1) * 128 + b]);
            fma2(a2[0][0], t0, A.x); fma2(a2[0][1], t0, A.y);
            fma2(a2[0][2], t0, B.x); fma2(a2[0][3], t0, B.y);
            fma2(a2[1][0], t1, A.x); fma2(a2[1][1], t1, A.y);
            fma2(a2[1][2], t1, B.x); fma2(a2[1][3], t1, B.y);
        }

        size_t obase = (img < BATCHN) ? (size_t)img * 8192
                                      : (size_t)(img - BATCHN) * 8192 + 4096;
        float* op = out + obase;
#pragma unroll
        for (int i = 0; i < 2; i++) {
            int n = nh * 2 + i;
            ulonglong2 v0; v0.x = a2[i][0]; v0.y = a2[i][1];
            ulonglong2 v1; v1.x = a2[i][2]; v1.y = a2[i][3];
            *(ulonglong2*)(op + n * 64 + 4 * g)      = v0;
            *(ulonglong2*)(op + n * 64 + 4 * g + 32) = v1;
        }
        __syncthreads();   // protect sT before next image's writes
    }
}

// ======================= launch =======================
extern "C" void kernel_launch(void* const* d_in, const int* in_sizes, int n_in,
                              void* d_out, int out_size) {
    const float* x  = (const float*)d_in[0];
    const float* xh = (const float*)d_in[1];
    const float* h  = (const float*)d_in[2];
    const float* W  = (const float*)d_in[3];
    const float* b  = (const float*)d_in[4];
    float* out = (float*)d_out;

    setup_kernel<<<1, 256>>>(h, W, b);

    cudaFuncSetAttribute(main_kernel, cudaFuncAttributeMaxDynamicSharedMemorySize, SMEM_TOTAL);

    int dev = 0, sm = 148;
    cudaGetDevice(&dev);
    cudaDeviceGetAttribute(&sm, cudaDevAttrMultiProcessorCount, dev);
    int grid = 2 * sm;              // 2 CTAs per SM
    if (grid < 2) grid = 296;
    if (grid > NIMG) grid = NIMG;

    main_kernel<<<grid, 256, SMEM_TOTAL>>>(x, xh, out, grid);
}

// round 7
// speedup vs baseline: 1.1129x; 1.1129x over previous
#include <cuda_runtime.h>
#include <cstdint>

#define BATCHN 1024
#define NIMG   2048

// ---- smem layout (bytes) ----
#define SM_Z     0          // 2 x 65536 z buffers
#define SM_FYT   131072     // FYT[a][n] 128x64 f32 = 32768
#define SM_FXT   163840     // FXT[b][m] 128x64 f32 = 32768
#define SM_T     196608     // 32 np-rows x 129 ull = 33024
#define SM_MBAR  229632     // 2 mbarriers
#define SMEM_TOTAL 229648

typedef unsigned long long ull;

__device__ float g_FYT[128 * 64];   // FYT[a][n] = F_Y[n][a], normalized, gamma folded
__device__ float g_FXT[128 * 64];   // FXT[b][m] = F_X[m][b], normalized

// ======================= setup kernel =======================
__global__ void setup_kernel(const float* __restrict__ hrow,
                             const float* __restrict__ W,
                             const float* __restrict__ bias) {
    __shared__ float red[256];
    __shared__ float sc[8];
    int tid = threadIdx.x;

    for (int j = 0; j < 5; j++) {
        float s = 0.f;
        for (int k = tid; k < 1024; k += 256) s += hrow[k] * W[j * 1024 + k];
        red[tid] = s; __syncthreads();
        for (int o = 128; o > 0; o >>= 1) { if (tid < o) red[tid] += red[tid + o]; __syncthreads(); }
        if (tid == 0) sc[j] = red[0] + bias[j];
        __syncthreads();
    }

    if (tid == 0) {
        float gtX = sc[0], gtY = sc[1], log_var = sc[2], log_dt = sc[3], lg = sc[4];
        sc[0] = 129.f * (gtX + 1.f) * 0.5f;          // g_X
        sc[1] = 129.f * (gtY + 1.f) * 0.5f;          // g_Y
        sc[2] = expf(log_var + 1e-8f);               // var
        sc[3] = expf(log_dt) * (127.f / 63.f);       // d
        sc[4] = expf(lg);                            // gamma
    }
    __syncthreads();
    float gX = sc[0], gY = sc[1], var = sc[2], dd = sc[3], gamma = sc[4];

    // F_Y, stored transposed: g_FYT[a*64 + n]
    float partY = 0.f;
    for (int idx = tid; idx < 8192; idx += 256) {
        int n = idx >> 7, c = idx & 127;              // c = a
        float mu = gY + ((float)n - 32.5f) * dd;
        float df = (float)c - mu;
        float e = expf(-(df * df) / (2.0f * var));
        g_FYT[c * 64 + n] = e; partY += e;
    }
    red[tid] = partY; __syncthreads();
    for (int o = 128; o > 0; o >>= 1) { if (tid < o) red[tid] += red[tid + o]; __syncthreads(); }
    if (tid == 0) sc[5] = red[0];
    __syncthreads();

    // F_X, stored transposed: g_FXT[b*64 + m]
    float partX = 0.f;
    for (int idx = tid; idx < 8192; idx += 256) {
        int m = idx >> 7, c = idx & 127;              // c = b
        float mu = gX + ((float)m - 32.5f) * dd;
        float df = (float)c - mu;
        float e = expf(-(df * df) / (2.0f * var));
        g_FXT[c * 64 + m] = e; partX += e;
    }
    red[tid] = partX; __syncthreads();
    for (int o = 128; o > 0; o >>= 1) { if (tid < o) red[tid] += red[tid + o]; __syncthreads(); }
    if (tid == 0) sc[6] = red[0];
    __syncthreads();

    float sY = gamma / sc[5];
    float sX = 1.0f / sc[6];
    for (int idx = tid; idx < 8192; idx += 256) {
        g_FYT[idx] *= sY;
        g_FXT[idx] *= sX;
    }
}

// ======================= helpers =======================
__device__ __forceinline__ uint32_t smem_u32(const void* p) {
    uint32_t a;
    asm("{ .reg .u64 t; cvta.to.shared.u64 t, %1; cvt.u32.u64 %0, t; }" : "=r"(a) : "l"(p));
    return a;
}
__device__ __forceinline__ ull dup2(float f) {
    ull r;
    asm("mov.b64 %0, {%1, %1};" : "=l"(r) : "f"(f));
    return r;
}
__device__ __forceinline__ void unpack2(ull v, float& lo, float& hi) {
    asm("mov.b64 {%0, %1}, %2;" : "=f"(lo), "=f"(hi) : "l"(v));
}
__device__ __forceinline__ void fma2(ull& c, ull a, ull b) {
    asm("fma.rn.f32x2 %0, %1, %2, %0;" : "+l"(c) : "l"(a), "l"(b));
}
__device__ __forceinline__ void mbar_wait(uint32_t addr, uint32_t parity) {
    asm volatile(
        "{\n\t.reg .pred P;\n\t"
        "LAB_%=:\n\t"
        "mbarrier.try_wait.parity.acquire.cta.shared::cta.b64 P, [%0], %1, 0x989680;\n\t"
        "@P bra.uni DONE_%=;\n\t"
        "bra.uni LAB_%=;\n\t"
        "DONE_%=:\n\t}"
        :: "r"(addr), "r"(parity) : "memory");
}
__device__ __forceinline__ void bulk_load(uint32_t dst, const float* src, uint32_t mbar) {
    asm volatile("mbarrier.arrive.expect_tx.shared.b64 _, [%0], %1;"
                 :: "r"(mbar), "r"(65536u) : "memory");
    asm volatile("cp.async.bulk.shared::cta.global.mbarrier::complete_tx::bytes [%0], [%1], %2, [%3];"
                 :: "r"(dst), "l"(src), "r"(65536u), "r"(mbar) : "memory");
}
// bank-spread swizzle on b (bits 2-3 ^= bits 4-5); bijection, pure f(b)
__device__ __forceinline__ int swz(int b) { return b ^ (((b >> 4) & 3) << 2); }

// ======================= main kernel =======================
__global__ void __launch_bounds__(256, 1)
main_kernel(const float* __restrict__ x, const float* __restrict__ xh,
            float* __restrict__ out, int grid) {
    extern __shared__ __align__(16) char smem[];
    float* sFYT = (float*)(smem + SM_FYT);
    float* sFXT = (float*)(smem + SM_FXT);
    ull*   sTp  = (ull*)(smem + SM_T);
    int tid = threadIdx.x;

    // stage filters into smem
    for (int i = tid; i < 8192; i += 256) { sFYT[i] = g_FYT[i]; sFXT[i] = g_FXT[i]; }

    uint32_t mb  = smem_u32(smem + SM_MBAR);
    uint32_t zsm = smem_u32(smem + SM_Z);
    if (tid == 0) {
        asm volatile("mbarrier.init.shared.b64 [%0], 1;" :: "r"(mb));
        asm volatile("mbarrier.init.shared.b64 [%0], 1;" :: "r"(mb + 8));
        asm volatile("fence.proxy.async.shared::cta;" ::: "memory");
    }
    __syncthreads();

    int img0 = blockIdx.x;
    if (tid == 0 && img0 < NIMG) {
        const float* src = (img0 < BATCHN) ? x + (size_t)img0 * 16384
                                           : xh + (size_t)(img0 - BATCHN) * 16384;
        bulk_load(zsm, src, mb);
    }

    const int ny = tid >> 5, bx = tid & 31;   // stage-1: warp-uniform ny
    const int ng = tid & 15, mx = tid >> 4;   // stage-2

    int it = 0;
    for (int img = img0; img < NIMG; img += grid, it++) {
        int buf = it & 1;

        // prefetch next image into other buffer (freed by previous iteration's sync)
        int nxt = img + grid;
        if (tid == 0 && nxt < NIMG) {
            const float* src = (nxt < BATCHN) ? x + (size_t)nxt * 16384
                                              : xh + (size_t)(nxt - BATCHN) * 16384;
            bulk_load(zsm + (buf ^ 1) * 65536u, src, mb + (buf ^ 1) * 8);
        }

        mbar_wait(mb + buf * 8, (uint32_t)((it >> 1) & 1));
        const float* zb = (const float*)(smem + SM_Z + buf * 65536);

        // ---- stage 1: t-pairs[np][b] = sum_a FYT_pair[a][np] * z[a][b] ----
        ull acc[4][4];
#pragma unroll
        for (int p = 0; p < 4; p++)
#pragma unroll
            for (int j = 0; j < 4; j++) acc[p][j] = 0ull;

#pragma unroll 4
        for (int a = 0; a < 128; a++) {
            float4 Z = *(const float4*)(zb + a * 128 + 4 * bx);
            ulonglong2 A = *(const ulonglong2*)(sFYT + a * 64 + 8 * ny);
            ulonglong2 B = *(const ulonglong2*)(sFYT + a * 64 + 8 * ny + 4);
            ull d0 = dup2(Z.x), d1 = dup2(Z.y), d2 = dup2(Z.z), d3 = dup2(Z.w);
            fma2(acc[0][0], A.x, d0); fma2(acc[0][1], A.x, d1);
            fma2(acc[0][2], A.x, d2); fma2(acc[0][3], A.x, d3);
            fma2(acc[1][0], A.y, d0); fma2(acc[1][1], A.y, d1);
            fma2(acc[1][2], A.y, d2); fma2(acc[1][3], A.y, d3);
            fma2(acc[2][0], B.x, d0); fma2(acc[2][1], B.x, d1);
            fma2(acc[2][2], B.x, d2); fma2(acc[2][3], B.x, d3);
            fma2(acc[3][0], B.y, d0); fma2(acc[3][1], B.y, d1);
            fma2(acc[3][2], B.y, d2); fma2(acc[3][3], B.y, d3);
        }

        // store t-pairs: row np = 4*ny+p (pair of n rows), col b (swizzled)
#pragma unroll
        for (int p = 0; p < 4; p++)
#pragma unroll
            for (int j = 0; j < 4; j++) {
                int b = 4 * bx + j;
                sTp[(4 * ny + p) * 129 + swz(b)] = acc[p][j];
            }
        __syncthreads();

        // ---- stage 2: out-pair[np][m] = sum_b t-pair[np][b] * FXT[b][m] ----
        ull a2[2][4];
#pragma unroll
        for (int i = 0; i < 2; i++)
#pragma unroll
            for (int j = 0; j < 4; j++) a2[i][j] = 0ull;

#pragma unroll 4
        for (int b = 0; b < 128; b++) {
            int sw = swz(b);
            ull t0 = sTp[ng * 129 + sw];
            ull t1 = sTp[(ng + 16) * 129 + sw];
            float4 F = *(const float4*)(sFXT + b * 64 + 4 * mx);
            ull f0 = dup2(F.x), f1 = dup2(F.y), f2 = dup2(F.z), f3 = dup2(F.w);
            fma2(a2[0][0], t0, f0); fma2(a2[0][1], t0, f1);
            fma2(a2[0][2], t0, f2); fma2(a2[0][3], t0, f3);
            fma2(a2[1][0], t1, f0); fma2(a2[1][1], t1, f1);
            fma2(a2[1][2], t1, f2); fma2(a2[1][3], t1, f3);
        }

        size_t obase = (img < BATCHN) ? (size_t)img * 8192
                                      : (size_t)(img - BATCHN) * 8192 + 4096;
        float* op = out + obase;
#pragma unroll
        for (int i = 0; i < 2; i++) {
            int n0 = 2 * (ng + 16 * i);   // even row; pair covers n0, n0+1
            float lo0, hi0, lo1, hi1, lo2, hi2, lo3, hi3;
            unpack2(a2[i][0], lo0, hi0);
            unpack2(a2[i][1], lo1, hi1);
            unpack2(a2[i][2], lo2, hi2);
            unpack2(a2[i][3], lo3, hi3);
            float4 v0; v0.x = lo0; v0.y = lo1; v0.z = lo2; v0.w = lo3;
            float4 v1; v1.x = hi0; v1.y = hi1; v1.z = hi2; v1.w = hi3;
            *(float4*)(op + (size_t)n0 * 64 + 4 * mx)       = v0;
            *(float4*)(op + (size_t)(n0 + 1) * 64 + 4 * mx) = v1;
        }
        __syncthreads();   // protect sTp before next image's stage-1 stores
    }
}

// ======================= launch =======================
extern "C" void kernel_launch(void* const* d_in, const int* in_sizes, int n_in,
                              void* d_out, int out_size) {
    const float* x  = (const float*)d_in[0];
    const float* xh = (const float*)d_in[1];
    const float* h  = (const float*)d_in[2];
    const float* W  = (const float*)d_in[3];
    const float* b  = (const float*)d_in[4];
    float* out = (float*)d_out;

    setup_kernel<<<1, 256>>>(h, W, b);

    cudaFuncSetAttribute(main_kernel, cudaFuncAttributeMaxDynamicSharedMemorySize, SMEM_TOTAL);

    int dev = 0, sm = 148;
    cudaGetDevice(&dev);
    cudaDeviceGetAttribute(&sm, cudaDevAttrMultiProcessorCount, dev);
    int grid = sm;
    if (grid < 1) grid = 148;
    if (grid > NIMG) grid = NIMG;

    main_kernel<<<grid, 256, SMEM_TOTAL>>>(x, xh, out, grid);
}

// round 8
// speedup vs baseline: 1.1777x; 1.0583x over previous
#include <cuda_runtime.h>
#include <cstdint>

#define BATCHN 1024
#define NIMG   2048

// ---- smem layout (bytes) ----
#define SM_Z     0          // 2 x 65536 z buffers
#define SM_FYT   131072     // FYT[a][n] 128x64 f32 = 32768
#define SM_FXT   163840     // FXT[b][m] 128x64 f32 = 32768
#define SM_T     196608     // 32 np-rows x 129 ull = 33024
#define SM_MBAR  229632     // 2 mbarriers
#define SMEM_TOTAL 229648

typedef unsigned long long ull;

__device__ float g_FYT[128 * 64];   // FYT[a][n] = F_Y[n][a], normalized, gamma folded
__device__ float g_FXT[128 * 64];   // FXT[b][m] = F_X[m][b], normalized

// ======================= setup kernel =======================
__global__ void setup_kernel(const float* __restrict__ hrow,
                             const float* __restrict__ W,
                             const float* __restrict__ bias) {
    __shared__ float red[256];
    __shared__ float sc[8];
    int tid = threadIdx.x;

    for (int j = 0; j < 5; j++) {
        float s = 0.f;
        for (int k = tid; k < 1024; k += 256) s += hrow[k] * W[j * 1024 + k];
        red[tid] = s; __syncthreads();
        for (int o = 128; o > 0; o >>= 1) { if (tid < o) red[tid] += red[tid + o]; __syncthreads(); }
        if (tid == 0) sc[j] = red[0] + bias[j];
        __syncthreads();
    }

    if (tid == 0) {
        float gtX = sc[0], gtY = sc[1], log_var = sc[2], log_dt = sc[3], lg = sc[4];
        sc[0] = 129.f * (gtX + 1.f) * 0.5f;          // g_X
        sc[1] = 129.f * (gtY + 1.f) * 0.5f;          // g_Y
        sc[2] = expf(log_var + 1e-8f);               // var
        sc[3] = expf(log_dt) * (127.f / 63.f);       // d
        sc[4] = expf(lg);                            // gamma
    }
    __syncthreads();
    float gX = sc[0], gY = sc[1], var = sc[2], dd = sc[3], gamma = sc[4];

    // F_Y, stored transposed: g_FYT[a*64 + n]
    float partY = 0.f;
    for (int idx = tid; idx < 8192; idx += 256) {
        int n = idx >> 7, c = idx & 127;              // c = a
        float mu = gY + ((float)n - 32.5f) * dd;
        float df = (float)c - mu;
        float e = expf(-(df * df) / (2.0f * var));
        g_FYT[c * 64 + n] = e; partY += e;
    }
    red[tid] = partY; __syncthreads();
    for (int o = 128; o > 0; o >>= 1) { if (tid < o) red[tid] += red[tid + o]; __syncthreads(); }
    if (tid == 0) sc[5] = red[0];
    __syncthreads();

    // F_X, stored transposed: g_FXT[b*64 + m]
    float partX = 0.f;
    for (int idx = tid; idx < 8192; idx += 256) {
        int m = idx >> 7, c = idx & 127;              // c = b
        float mu = gX + ((float)m - 32.5f) * dd;
        float df = (float)c - mu;
        float e = expf(-(df * df) / (2.0f * var));
        g_FXT[c * 64 + m] = e; partX += e;
    }
    red[tid] = partX; __syncthreads();
    for (int o = 128; o > 0; o >>= 1) { if (tid < o) red[tid] += red[tid + o]; __syncthreads(); }
    if (tid == 0) sc[6] = red[0];
    __syncthreads();

    float sY = gamma / sc[5];
    float sX = 1.0f / sc[6];
    for (int idx = tid; idx < 8192; idx += 256) {
        g_FYT[idx] *= sY;
        g_FXT[idx] *= sX;
    }
}

// ======================= helpers =======================
__device__ __forceinline__ uint32_t smem_u32(const void* p) {
    uint32_t a;
    asm("{ .reg .u64 t; cvta.to.shared.u64 t, %1; cvt.u32.u64 %0, t; }" : "=r"(a) : "l"(p));
    return a;
}
__device__ __forceinline__ ull dup2(float f) {
    ull r;
    asm("mov.b64 %0, {%1, %1};" : "=l"(r) : "f"(f));
    return r;
}
__device__ __forceinline__ void unpack2(ull v, float& lo, float& hi) {
    asm("mov.b64 {%0, %1}, %2;" : "=f"(lo), "=f"(hi) : "l"(v));
}
__device__ __forceinline__ void fma2(ull& c, ull a, ull b) {
    asm("fma.rn.f32x2 %0, %1, %2, %0;" : "+l"(c) : "l"(a), "l"(b));
}
__device__ __forceinline__ void mbar_wait(uint32_t addr, uint32_t parity) {
    asm volatile(
        "{\n\t.reg .pred P;\n\t"
        "LAB_%=:\n\t"
        "mbarrier.try_wait.parity.acquire.cta.shared::cta.b64 P, [%0], %1, 0x989680;\n\t"
        "@P bra.uni DONE_%=;\n\t"
        "bra.uni LAB_%=;\n\t"
        "DONE_%=:\n\t}"
        :: "r"(addr), "r"(parity) : "memory");
}
__device__ __forceinline__ void bulk_load(uint32_t dst, const float* src, uint32_t mbar) {
    asm volatile("mbarrier.arrive.expect_tx.shared.b64 _, [%0], %1;"
                 :: "r"(mbar), "r"(65536u) : "memory");
    asm volatile("cp.async.bulk.shared::cta.global.mbarrier::complete_tx::bytes [%0], [%1], %2, [%3];"
                 :: "r"(dst), "l"(src), "r"(65536u), "r"(mbar) : "memory");
}
// bank-spread swizzle on b (bits 2-3 ^= bits 4-5); bijection, pure f(b)
__device__ __forceinline__ int swz(int b) { return b ^ (((b >> 4) & 3) << 2); }

// ======================= main kernel =======================
__global__ void __launch_bounds__(256, 1)
main_kernel(const float* __restrict__ x, const float* __restrict__ xh,
            float* __restrict__ out, int grid) {
    extern __shared__ __align__(16) char smem[];
    float* sFYT = (float*)(smem + SM_FYT);
    float* sFXT = (float*)(smem + SM_FXT);
    ull*   sTp  = (ull*)(smem + SM_T);
    int tid = threadIdx.x;

    // stage filters into smem
    for (int i = tid; i < 8192; i += 256) { sFYT[i] = g_FYT[i]; sFXT[i] = g_FXT[i]; }

    uint32_t mb  = smem_u32(smem + SM_MBAR);
    uint32_t zsm = smem_u32(smem + SM_Z);
    if (tid == 0) {
        asm volatile("mbarrier.init.shared.b64 [%0], 1;" :: "r"(mb));
        asm volatile("mbarrier.init.shared.b64 [%0], 1;" :: "r"(mb + 8));
        asm volatile("fence.proxy.async.shared::cta;" ::: "memory");
    }
    __syncthreads();

    int img0 = blockIdx.x;
    if (tid == 0 && img0 < NIMG) {
        const float* src = (img0 < BATCHN) ? x + (size_t)img0 * 16384
                                           : xh + (size_t)(img0 - BATCHN) * 16384;
        bulk_load(zsm, src, mb);
    }

    const int ny = tid >> 5, bx = tid & 31;   // stage-1: warp-uniform ny
    const int ng = tid & 15, mx = tid >> 4;   // stage-2

    int it = 0;
    for (int img = img0; img < NIMG; img += grid, it++) {
        int buf = it & 1;

        // prefetch next image into other buffer (freed by previous iteration's sync)
        int nxt = img + grid;
        if (tid == 0 && nxt < NIMG) {
            const float* src = (nxt < BATCHN) ? x + (size_t)nxt * 16384
                                              : xh + (size_t)(nxt - BATCHN) * 16384;
            bulk_load(zsm + (buf ^ 1) * 65536u, src, mb + (buf ^ 1) * 8);
        }

        mbar_wait(mb + buf * 8, (uint32_t)((it >> 1) & 1));
        const float* zb = (const float*)(smem + SM_Z + buf * 65536);

        // ---- stage 1: t-pairs[np][b] = sum_a FYT_pair[a][np] * z[a][b] ----
        ull acc[4][4];
#pragma unroll
        for (int p = 0; p < 4; p++)
#pragma unroll
            for (int j = 0; j < 4; j++) acc[p][j] = 0ull;

#pragma unroll 4
        for (int a = 0; a < 128; a++) {
            float4 Z = *(const float4*)(zb + a * 128 + 4 * bx);
            ulonglong2 A = *(const ulonglong2*)(sFYT + a * 64 + 8 * ny);
            ulonglong2 B = *(const ulonglong2*)(sFYT + a * 64 + 8 * ny + 4);
            ull d0 = dup2(Z.x), d1 = dup2(Z.y), d2 = dup2(Z.z), d3 = dup2(Z.w);
            fma2(acc[0][0], A.x, d0); fma2(acc[0][1], A.x, d1);
            fma2(acc[0][2], A.x, d2); fma2(acc[0][3], A.x, d3);
            fma2(acc[1][0], A.y, d0); fma2(acc[1][1], A.y, d1);
            fma2(acc[1][2], A.y, d2); fma2(acc[1][3], A.y, d3);
            fma2(acc[2][0], B.x, d0); fma2(acc[2][1], B.x, d1);
            fma2(acc[2][2], B.x, d2); fma2(acc[2][3], B.x, d3);
            fma2(acc[3][0], B.y, d0); fma2(acc[3][1], B.y, d1);
            fma2(acc[3][2], B.y, d2); fma2(acc[3][3], B.y, d3);
        }

        // store t-pairs: row np = 4*ny+p (pair of n rows), col b (swizzled)
#pragma unroll
        for (int p = 0; p < 4; p++)
#pragma unroll
            for (int j = 0; j < 4; j++) {
                int b = 4 * bx + j;
                sTp[(4 * ny + p) * 129 + swz(b)] = acc[p][j];
            }
        __syncthreads();

        // ---- stage 2: out-pair[np][m] = sum_b t-pair[np][b] * FXT[b][m] ----
        ull a2[2][4];
#pragma unroll
        for (int i = 0; i < 2; i++)
#pragma unroll
            for (int j = 0; j < 4; j++) a2[i][j] = 0ull;

#pragma unroll 4
        for (int b = 0; b < 128; b++) {
            int sw = swz(b);
            ull t0 = sTp[ng * 129 + sw];
            ull t1 = sTp[(ng + 16) * 129 + sw];
            float4 F = *(const float4*)(sFXT + b * 64 + 4 * mx);
            ull f0 = dup2(F.x), f1 = dup2(F.y), f2 = dup2(F.z), f3 = dup2(F.w);
            fma2(a2[0][0], t0, f0); fma2(a2[0][1], t0, f1);
            fma2(a2[0][2], t0, f2); fma2(a2[0][3], t0, f3);
            fma2(a2[1][0], t1, f0); fma2(a2[1][1], t1, f1);
            fma2(a2[1][2], t1, f2); fma2(a2[1][3], t1, f3);
        }

        size_t obase = (img < BATCHN) ? (size_t)img * 8192
                                      : (size_t)(img - BATCHN) * 8192 + 4096;
        float* op = out + obase;
#pragma unroll
        for (int i = 0; i < 2; i++) {
            int n0 = 2 * (ng + 16 * i);   // even row; pair covers n0, n0+1
            float lo0, hi0, lo1, hi1, lo2, hi2, lo3, hi3;
            unpack2(a2[i][0], lo0, hi0);
            unpack2(a2[i][1], lo1, hi1);
            unpack2(a2[i][2], lo2, hi2);
            unpack2(a2[i][3], lo3, hi3);
            float4 v0; v0.x = lo0; v0.y = lo1; v0.z = lo2; v0.w = lo3;
            float4 v1; v1.x = hi0; v1.y = hi1; v1.z = hi2; v1.w = hi3;
            *(float4*)(op + (size_t)n0 * 64 + 4 * mx)       = v0;
            *(float4*)(op + (size_t)(n0 + 1) * 64 + 4 * mx) = v1;
        }
        __syncthreads();   // protect sTp before next image's stage-1 stores
    }
}

// ======================= launch =======================
extern "C" void kernel_launch(void* const* d_in, const int* in_sizes, int n_in,
                              void* d_out, int out_size) {
    const float* x  = (const float*)d_in[0];
    const float* xh = (const float*)d_in[1];
    const float* h  = (const float*)d_in[2];
    const float* W  = (const float*)d_in[3];
    const float* b  = (const float*)d_in[4];
    float* out = (float*)d_out;

    setup_kernel<<<1, 256>>>(h, W, b);

    cudaFuncSetAttribute(main_kernel, cudaFuncAttributeMaxDynamicSharedMemorySize, SMEM_TOTAL);

    int dev = 0, sm = 148;
    cudaGetDevice(&dev);
    cudaDeviceGetAttribute(&sm, cudaDevAttrMultiProcessorCount, dev);
    int grid = sm;
    if (grid < 1) grid = 148;
    if (grid > NIMG) grid = NIMG;

    main_kernel<<<grid, 256, SMEM_TOTAL>>>(x, xh, out, grid);
}

// round 10
// speedup vs baseline: 2.0248x; 1.7192x over previous
#include <cuda_runtime.h>
#include <cuda_bf16.h>
#include <cstdint>

#define BATCHN 1024
#define NIMG   2048

// ---- smem layout (bytes) ----
#define SM_RING  0          // 2 x 16384 f32 z chunk ring (32 a-rows each)
#define SM_ZH    32768      // chunk z hi bf16, swizzled, 32x128 (8192)
#define SM_ZL    40960      // chunk z lo bf16 (8192)
#define SM_UHI   49152      // u hi bf16 [a][m], stride 136 bf16 (272B) x128 rows (34816)
#define SM_ULO   83968      // u lo
#define SM_MBAR  118784
#define SMEM_TOTAL 118816

typedef unsigned int u32;

// fragment tables (precomputed by setup kernel)
__device__ __align__(16) uint4 g_FXfrag[8 * 8 * 32];       // (j,s,lane): {b0h,b1h,b0l,b1l}
__device__ __align__(16) uint4 g_FYfrag[4 * 8 * 32 * 2];   // ((r,s,lane)*2+{hi,lo}): {a0,a1,a2,a3}

// ======================= helpers (host+device) =======================
__device__ __forceinline__ u32 prmt_hi(u32 a, u32 b) {   // low16=a.hi16, high16=b.hi16
    u32 r;
    asm("prmt.b32 %0, %1, %2, 0x7632;" : "=r"(r) : "r"(a), "r"(b));
    return r;
}
__device__ __forceinline__ u32 pack_lo2(float e0, float e1) {   // low16=bf16(e0), high16=bf16(e1)
    u32 r;
    asm("cvt.rn.bf16x2.f32 %0, %1, %2;" : "=r"(r) : "f"(e1), "f"(e0));
    return r;
}
__device__ __forceinline__ float hif(float x) {
    return __uint_as_float(__float_as_uint(x) & 0xFFFF0000u);
}
__device__ __forceinline__ u32 zswz(int row, int seg) {   // byte offset in 32x256B plane
    return (u32)(row * 256 + ((seg ^ (row & 7) ^ (((row >> 3) & 1) << 3)) << 4));
}

// ======================= setup kernel =======================
__global__ void setup_kernel(const float* __restrict__ hrow,
                             const float* __restrict__ W,
                             const float* __restrict__ bias) {
    __shared__ float red[256];
    __shared__ float sc[8];
    int tid = threadIdx.x;

    for (int j = 0; j < 5; j++) {
        float s = 0.f;
        for (int k = tid; k < 1024; k += 256) s += hrow[k] * W[j * 1024 + k];
        red[tid] = s; __syncthreads();
        for (int o = 128; o > 0; o >>= 1) { if (tid < o) red[tid] += red[tid + o]; __syncthreads(); }
        if (tid == 0) sc[j] = red[0] + bias[j];
        __syncthreads();
    }

    if (tid == 0) {
        float gtX = sc[0], gtY = sc[1], log_var = sc[2], log_dt = sc[3], lg = sc[4];
        sc[0] = 129.f * (gtX + 1.f) * 0.5f;
        sc[1] = 129.f * (gtY + 1.f) * 0.5f;
        sc[2] = expf(log_var + 1e-8f);
        sc[3] = expf(log_dt) * (127.f / 63.f);
        sc[4] = expf(lg);
    }
    __syncthreads();
    float gX = sc[0], gY = sc[1], var = sc[2], dd = sc[3], gamma = sc[4];
    float inv2v = 1.0f / (2.0f * var);

    // global sums
    float pY = 0.f, pX = 0.f;
    for (int idx = tid; idx < 8192; idx += 256) {
        int n = idx >> 7, c = idx & 127;
        float dY = (float)c - (gY + ((float)n - 32.5f) * dd);
        pY += expf(-dY * dY * inv2v);
        float dX = (float)c - (gX + ((float)n - 32.5f) * dd);
        pX += expf(-dX * dX * inv2v);
    }
    red[tid] = pY; __syncthreads();
    for (int o = 128; o > 0; o >>= 1) { if (tid < o) red[tid] += red[tid + o]; __syncthreads(); }
    if (tid == 0) sc[5] = red[0];
    __syncthreads();
    red[tid] = pX; __syncthreads();
    for (int o = 128; o > 0; o >>= 1) { if (tid < o) red[tid] += red[tid + o]; __syncthreads(); }
    if (tid == 0) sc[6] = red[0];
    __syncthreads();

    float sY = gamma / sc[5];
    float sX = 1.0f / sc[6];

    // FX B-fragments: frag(j,s) gives B[k=b][n=m] col-major; b0={FX(m,b0),FX(m,b0+1)}, b1=cols+8
    for (int e = tid; e < 2048; e += 256) {
        int lane = e & 31, s = (e >> 5) & 7, j = e >> 8;
        int gid = lane >> 2, t4 = lane & 3;
        int m = 8 * j + gid;
        float mu = gX + ((float)m - 32.5f) * dd;
        int b0 = 16 * s + t4 * 2;
        float d0 = (float)b0 - mu,       d1 = (float)(b0 + 1) - mu;
        float d2 = (float)(b0 + 8) - mu, d3 = (float)(b0 + 9) - mu;
        float x0 = expf(-d0 * d0 * inv2v) * sX;
        float x1 = expf(-d1 * d1 * inv2v) * sX;
        float x2 = expf(-d2 * d2 * inv2v) * sX;
        float x3 = expf(-d3 * d3 * inv2v) * sX;
        uint4 v;
        v.x = prmt_hi(__float_as_uint(x0), __float_as_uint(x1));
        v.y = prmt_hi(__float_as_uint(x2), __float_as_uint(x3));
        v.z = pack_lo2(x0 - hif(x0), x1 - hif(x1));
        v.w = pack_lo2(x2 - hif(x2), x3 - hif(x3));
        g_FXfrag[e] = v;
    }

    // FY A-fragments: frag(r,s): a0=(n=16r+gid, a=16s+t4*2,+1) a1=row+8 a2=col+8 a3=both+8
    for (int e = tid; e < 1024; e += 256) {
        int lane = e & 31, s = (e >> 5) & 7, r = e >> 8;
        int gid = lane >> 2, t4 = lane & 3;
        int n0 = 16 * r + gid, n1 = n0 + 8;
        float mu0 = gY + ((float)n0 - 32.5f) * dd;
        float mu1 = gY + ((float)n1 - 32.5f) * dd;
        int a0 = 16 * s + t4 * 2;
        float y[8];
        y[0] = expf(-((float)a0 - mu0)       * ((float)a0 - mu0)       * inv2v) * sY;
        y[1] = expf(-((float)(a0+1) - mu0)   * ((float)(a0+1) - mu0)   * inv2v) * sY;
        y[2] = expf(-((float)a0 - mu1)       * ((float)a0 - mu1)       * inv2v) * sY;
        y[3] = expf(-((float)(a0+1) - mu1)   * ((float)(a0+1) - mu1)   * inv2v) * sY;
        y[4] = expf(-((float)(a0+8) - mu0)   * ((float)(a0+8) - mu0)   * inv2v) * sY;
        y[5] = expf(-((float)(a0+9) - mu0)   * ((float)(a0+9) - mu0)   * inv2v) * sY;
        y[6] = expf(-((float)(a0+8) - mu1)   * ((float)(a0+8) - mu1)   * inv2v) * sY;
        y[7] = expf(-((float)(a0+9) - mu1)   * ((float)(a0+9) - mu1)   * inv2v) * sY;
        uint4 hi, lo;
        hi.x = prmt_hi(__float_as_uint(y[0]), __float_as_uint(y[1]));   // a0
        hi.y = prmt_hi(__float_as_uint(y[2]), __float_as_uint(y[3]));   // a1
        hi.z = prmt_hi(__float_as_uint(y[4]), __float_as_uint(y[5]));   // a2
        hi.w = prmt_hi(__float_as_uint(y[6]), __float_as_uint(y[7]));   // a3
        lo.x = pack_lo2(y[0] - hif(y[0]), y[1] - hif(y[1]));
        lo.y = pack_lo2(y[2] - hif(y[2]), y[3] - hif(y[3]));
        lo.z = pack_lo2(y[4] - hif(y[4]), y[5] - hif(y[5]));
        lo.w = pack_lo2(y[6] - hif(y[6]), y[7] - hif(y[7]));
        g_FYfrag[2 * e]     = hi;
        g_FYfrag[2 * e + 1] = lo;
    }
}

// ======================= device helpers =======================
__device__ __forceinline__ u32 smem_u32(const void* p) {
    u32 a;
    asm("{ .reg .u64 t; cvta.to.shared.u64 t, %1; cvt.u32.u64 %0, t; }" : "=r"(a) : "l"(p));
    return a;
}
__device__ __forceinline__ void mbar_wait(u32 addr, u32 parity) {
    asm volatile(
        "{\n\t.reg .pred P;\n\t"
        "LAB_%=:\n\t"
        "mbarrier.try_wait.parity.acquire.cta.shared::cta.b64 P, [%0], %1, 0x989680;\n\t"
        "@P bra.uni DONE_%=;\n\t"
        "bra.uni LAB_%=;\n\t"
        "DONE_%=:\n\t}"
        :: "r"(addr), "r"(parity) : "memory");
}
__device__ __forceinline__ void bulk_load16k(u32 dst, const float* src, u32 mbar) {
    asm volatile("mbarrier.arrive.expect_tx.shared.b64 _, [%0], %1;"
                 :: "r"(mbar), "r"(16384u) : "memory");
    asm volatile("cp.async.bulk.shared::cta.global.mbarrier::complete_tx::bytes [%0], [%1], %2, [%3];"
                 :: "r"(dst), "l"(src), "r"(16384u), "r"(mbar) : "memory");
}
__device__ __forceinline__ void ldm_x4(u32& r0, u32& r1, u32& r2, u32& r3, u32 addr) {
    asm volatile("ldmatrix.sync.aligned.m8n8.x4.shared.b16 {%0,%1,%2,%3}, [%4];"
                 : "=r"(r0), "=r"(r1), "=r"(r2), "=r"(r3) : "r"(addr));
}
__device__ __forceinline__ void ldm_x2t(u32& r0, u32& r1, u32 addr) {
    asm volatile("ldmatrix.sync.aligned.m8n8.x2.trans.shared.b16 {%0,%1}, [%2];"
                 : "=r"(r0), "=r"(r1) : "r"(addr));
}
__device__ __forceinline__ void mma_bf16(float* c, u32 a0, u32 a1, u32 a2, u32 a3, u32 b0, u32 b1) {
    asm volatile(
        "mma.sync.aligned.m16n8k16.row.col.f32.bf16.bf16.f32 "
        "{%0,%1,%2,%3}, {%4,%5,%6,%7}, {%8,%9}, {%0,%1,%2,%3};"
        : "+f"(c[0]), "+f"(c[1]), "+f"(c[2]), "+f"(c[3])
        : "r"(a0), "r"(a1), "r"(a2), "r"(a3), "r"(b0), "r"(b1));
}
__device__ __forceinline__ const float* chunk_src(int ci, int img0, int grid,
                                                  const float* x, const float* xh, int& img) {
    img = img0 + (ci >> 2) * grid;
    const float* base = (img < BATCHN) ? x + (size_t)img * 16384
                                       : xh + (size_t)(img - BATCHN) * 16384;
    return base + (ci & 3) * 4096;
}

// ======================= main kernel =======================
__global__ void __launch_bounds__(256, 1)
main_kernel(const float* __restrict__ x, const float* __restrict__ xh,
            float* __restrict__ out, int grid) {
    extern __shared__ __align__(16) char smem[];
    int tid = threadIdx.x, wid = tid >> 5, lid = tid & 31;
    int gid = lid >> 2, t4 = lid & 3;

    u32 base = smem_u32(smem);
    u32 mbR0 = base + SM_MBAR, mbR1 = base + SM_MBAR + 8;
    if (tid == 0) {
        asm volatile("mbarrier.init.shared.b64 [%0], 1;" :: "r"(mbR0));
        asm volatile("mbarrier.init.shared.b64 [%0], 1;" :: "r"(mbR1));
        asm volatile("fence.proxy.async.shared::cta;" ::: "memory");
    }
    __syncthreads();

    // stage-1 warp mapping: ablock = wid>>2 (16 a-rows within chunk), nq = wid&3 (2 m-tiles)
    int ablock = wid >> 2, nq = wid & 3;
    // FX B-fragments -> persistent registers (used every chunk)
    uint4 fxA[8], fxB[8];
#pragma unroll
    for (int s = 0; s < 8; s++) {
        fxA[s] = __ldg(&g_FXfrag[((2 * nq) * 8 + s) * 32 + lid]);
        fxB[s] = __ldg(&g_FXfrag[((2 * nq + 1) * 8 + s) * 32 + lid]);
    }

    int img0 = blockIdx.x;
    if (tid == 0) {
        int im;
        const float* s0 = chunk_src(0, img0, grid, x, xh, im);
        if (im < NIMG) bulk_load16k(base + SM_RING, s0, mbR0);
        const float* s1 = chunk_src(1, img0, grid, x, xh, im);
        if (im < NIMG) bulk_load16k(base + SM_RING + 16384u, s1, mbR1);
    }

    // stage-1 ldmatrix lane address components
    int rowA = ablock * 16 + (lid & 7) + ((lid >> 3) & 1) * 8;
    int segb = lid >> 4;
    // stage-2 warp mapping
    int r2 = wid >> 1, jh = wid & 1;
    int krow = lid & 15;

    int it = 0;
    for (int img = img0; img < NIMG; img += grid, it++) {

        // ================= stage 1: four 32-row chunks =================
#pragma unroll 1
        for (int c = 0; c < 4; c++) {
            int ci = it * 4 + c;
            mbar_wait((ci & 1) ? mbR1 : mbR0, (u32)((ci >> 1) & 1));

            // ---- convert chunk f32 -> bf16 hi/lo swizzled planes ----
            {
                int r = tid >> 3, j8 = tid & 7;
                const float* zr = (const float*)(smem + SM_RING + (ci & 1) * 16384)
                                  + r * 128 + j8 * 16;
                float v[16];
                *(float4*)(v)      = *(const float4*)(zr);
                *(float4*)(v + 4)  = *(const float4*)(zr + 4);
                *(float4*)(v + 8)  = *(const float4*)(zr + 8);
                *(float4*)(v + 12) = *(const float4*)(zr + 12);
                u32 H[8], L[8];
#pragma unroll
                for (int p = 0; p < 8; p++) {
                    u32 b0 = __float_as_uint(v[2 * p]), b1 = __float_as_uint(v[2 * p + 1]);
                    H[p] = prmt_hi(b0, b1);
                    L[p] = pack_lo2(v[2 * p]     - __uint_as_float(b0 & 0xFFFF0000u),
                                    v[2 * p + 1] - __uint_as_float(b1 & 0xFFFF0000u));
                }
                u32 o0 = zswz(r, 2 * j8), o1 = zswz(r, 2 * j8 + 1);
                *(uint4*)(smem + SM_ZH + o0) = make_uint4(H[0], H[1], H[2], H[3]);
                *(uint4*)(smem + SM_ZH + o1) = make_uint4(H[4], H[5], H[6], H[7]);
                *(uint4*)(smem + SM_ZL + o0) = make_uint4(L[0], L[1], L[2], L[3]);
                *(uint4*)(smem + SM_ZL + o1) = make_uint4(L[4], L[5], L[6], L[7]);
            }
            __syncthreads();
            if (tid == 0) {
                int c2 = ci + 2, im;
                const float* s = chunk_src(c2, img0, grid, x, xh, im);
                if (im < NIMG) bulk_load16k(base + SM_RING + (c2 & 1) * 16384u, s,
                                            (c2 & 1) ? mbR1 : mbR0);
            }

            // ---- mma: u(16a x 16m per warp) ----
            float acc0[4] = {0.f, 0.f, 0.f, 0.f};
            float acc1[4] = {0.f, 0.f, 0.f, 0.f};
#pragma unroll
            for (int s = 0; s < 8; s++) {
                u32 sw = zswz(rowA, 2 * s + segb);
                u32 h0, h1, h2, h3, l0, l1, l2, l3;
                ldm_x4(h0, h1, h2, h3, base + SM_ZH + sw);
                ldm_x4(l0, l1, l2, l3, base + SM_ZL + sw);
                mma_bf16(acc0, h0, h1, h2, h3, fxA[s].x, fxA[s].y);   // hh
                mma_bf16(acc1, h0, h1, h2, h3, fxB[s].x, fxB[s].y);
                mma_bf16(acc0, h0, h1, h2, h3, fxA[s].z, fxA[s].w);   // hl
                mma_bf16(acc1, h0, h1, h2, h3, fxB[s].z, fxB[s].w);
                mma_bf16(acc0, l0, l1, l2, l3, fxA[s].x, fxA[s].y);   // lh
                mma_bf16(acc1, l0, l1, l2, l3, fxB[s].x, fxB[s].y);
            }

            // ---- epilogue: u rows -> bf16 hi/lo, stride 136 bf16 (272 B) ----
            {
                int ag0 = c * 32 + ablock * 16 + gid;      // rows ag0, ag0+8
#pragma unroll
                for (int jj = 0; jj < 2; jj++) {
                    float* A = jj ? acc1 : acc0;
                    int m = 8 * (2 * nq + jj) + t4 * 2;
                    u32 h0 = prmt_hi(__float_as_uint(A[0]), __float_as_uint(A[1]));
                    u32 l0 = pack_lo2(A[0] - hif(A[0]), A[1] - hif(A[1]));
                    u32 h1 = prmt_hi(__float_as_uint(A[2]), __float_as_uint(A[3]));
                    u32 l1 = pack_lo2(A[2] - hif(A[2]), A[3] - hif(A[3]));
                    *(u32*)(smem + SM_UHI + ag0 * 272 + m * 2)       = h0;
                    *(u32*)(smem + SM_UHI + (ag0 + 8) * 272 + m * 2) = h1;
                    *(u32*)(smem + SM_ULO + ag0 * 272 + m * 2)       = l0;
                    *(u32*)(smem + SM_ULO + (ag0 + 8) * 272 + m * 2) = l1;
                }
            }
            __syncthreads();
        }

        // ================= stage 2: out = FY @ u =================
        float a2[4][4];
#pragma unroll
        for (int jj = 0; jj < 4; jj++)
#pragma unroll
            for (int q = 0; q < 4; q++) a2[jj][q] = 0.f;

#pragma unroll
        for (int s = 0; s < 8; s++) {
            uint4 fyh = __ldg(&g_FYfrag[((r2 * 8 + s) * 32 + lid) * 2]);
            uint4 fyl = __ldg(&g_FYfrag[((r2 * 8 + s) * 32 + lid) * 2 + 1]);
            u32 rowoff = (u32)((16 * s + krow) * 272);
#pragma unroll
            for (int jj = 0; jj < 4; jj++) {
                int j = jh * 4 + jj;
                u32 bh0, bh1, bl0, bl1;
                ldm_x2t(bh0, bh1, base + SM_UHI + rowoff + j * 16);
                ldm_x2t(bl0, bl1, base + SM_ULO + rowoff + j * 16);
                mma_bf16(a2[jj], fyh.x, fyh.y, fyh.z, fyh.w, bh0, bh1);   // hh
                mma_bf16(a2[jj], fyh.x, fyh.y, fyh.z, fyh.w, bl0, bl1);   // hl
                mma_bf16(a2[jj], fyl.x, fyl.y, fyl.z, fyl.w, bh0, bh1);   // lh
            }
        }

        // ---- write out ----
        size_t obase = (img < BATCHN) ? (size_t)img * 8192
                                      : (size_t)(img - BATCHN) * 8192 + 4096;
        float* op = out + obase;
        int n0 = 16 * r2 + gid;
#pragma unroll
        for (int jj = 0; jj < 4; jj++) {
            int m = 8 * (jh * 4 + jj) + t4 * 2;
            float2 v0; v0.x = a2[jj][0]; v0.y = a2[jj][1];
            float2 v1; v1.x = a2[jj][2]; v1.y = a2[jj][3];
            *(float2*)(op + (size_t)n0 * 64 + m)       = v0;
            *(float2*)(op + (size_t)(n0 + 8) * 64 + m) = v1;
        }
        __syncthreads();   // u reuse safety before next image's stage-1 epilogue
    }
}

// ======================= launch =======================
extern "C" void kernel_launch(void* const* d_in, const int* in_sizes, int n_in,
                              void* d_out, int out_size) {
    const float* x  = (const float*)d_in[0];
    const float* xh = (const float*)d_in[1];
    const float* h  = (const float*)d_in[2];
    const float* W  = (const float*)d_in[3];
    const float* b  = (const float*)d_in[4];
    float* out = (float*)d_out;

    setup_kernel<<<1, 256>>>(h, W, b);

    cudaFuncSetAttribute(main_kernel, cudaFuncAttributeMaxDynamicSharedMemorySize, SMEM_TOTAL);

    int dev = 0, sm = 148;
    cudaGetDevice(&dev);
    cudaDeviceGetAttribute(&sm, cudaDevAttrMultiProcessorCount, dev);
    int grid = sm;
    if (grid < 1) grid = 148;
    if (grid > NIMG) grid = NIMG;

    main_kernel<<<grid, 256, SMEM_TOTAL>>>(x, xh, out, grid);
}